// round 7
// baseline (speedup 1.0000x reference)
#include <cuda_runtime.h>
#include <math.h>

#define NUM_NODES   8192
#define MEME_DIM    64
#define VISION      2048
#define K_IN        32
#define VOCAB_N     256
#define G_TOT       (NUM_NODES * MEME_DIM)
#define TILE_FLOATS (MEME_DIM * VOCAB_N)        // 16384 floats
#define TILE_BYTES  (TILE_FLOATS * 4)           // 65536 bytes
#define GRID_P      148                          // persistent CTAs (1/SM)
#define RTHREADS    512
#define NBUF        3

// Scratch (device globals; no allocation allowed)
__device__ float  d_g_raw[G_TOT];
__device__ float2 d_partials[NUM_NODES];
__device__ float  d_stats[2];  // [0]=mean, [1]=inv_std

// ---------------------------------------------------------------------------
// PTX helpers
// ---------------------------------------------------------------------------
__device__ __forceinline__ unsigned smem_u32(const void* p) {
    unsigned r;
    asm("{ .reg .u64 t; cvta.to.shared.u64 t, %1; cvt.u32.u64 %0, t; }"
        : "=r"(r) : "l"(p));
    return r;
}
__device__ __forceinline__ void mbar_init(unsigned addr, unsigned count) {
    asm volatile("mbarrier.init.shared.b64 [%0], %1;" :: "r"(addr), "r"(count) : "memory");
}
__device__ __forceinline__ void mbar_expect_tx(unsigned addr, unsigned bytes) {
    asm volatile("mbarrier.arrive.expect_tx.shared.b64 _, [%0], %1;"
                 :: "r"(addr), "r"(bytes) : "memory");
}
__device__ __forceinline__ void bulk_ldgsts(unsigned dst_smem, const void* src_gmem,
                                            unsigned bytes, unsigned mbar) {
    asm volatile(
        "cp.async.bulk.shared::cta.global.mbarrier::complete_tx::bytes "
        "[%0], [%1], %2, [%3];"
        :: "r"(dst_smem), "l"(src_gmem), "r"(bytes), "r"(mbar) : "memory");
}
__device__ __forceinline__ void mbar_wait(unsigned addr, unsigned phase) {
    asm volatile(
        "{\n\t"
        ".reg .pred P;\n\t"
        "WAIT_%=:\n\t"
        "mbarrier.try_wait.parity.acquire.cta.shared::cta.b64 P, [%0], %1, 0x989680;\n\t"
        "@!P bra WAIT_%=;\n\t"
        "}"
        :: "r"(addr), "r"(phase) : "memory");
}
__device__ __forceinline__ float fast_tanh(float x) {
    float r;
    asm("tanh.approx.f32 %0, %1;" : "=f"(r) : "f"(x));
    return r;
}

// ---------------------------------------------------------------------------
// Kernel 1: gather + mean. 2 nodes per 256-thread block; 4-way MLP per thread.
// ---------------------------------------------------------------------------
__global__ __launch_bounds__(256) void gather_kernel(
    const float* __restrict__ x,          // [2048, 64]
    const float* __restrict__ memes,      // [8192, 64]
    const int*   __restrict__ idx)        // [8192, 32]
{
    const int tid  = threadIdx.x;
    const int half = tid >> 7;
    const int t    = tid & 127;
    const int n    = blockIdx.x * 2 + half;
    const int f4   = t & 15;
    const int kb   = t >> 4;

    const int* ri = idx + (size_t)n * K_IN;

    float4 acc = make_float4(0.f, 0.f, 0.f, 0.f);
#pragma unroll
    for (int j = 0; j < 4; j++) {
        int r = __ldg(ri + kb + 8 * j);
        const float4* src = (r < VISION)
            ? (const float4*)(x + (size_t)r * MEME_DIM)
            : (const float4*)(memes + (size_t)(r - VISION) * MEME_DIM);
        float4 v = __ldg(src + f4);
        acc.x += v.x; acc.y += v.y; acc.z += v.z; acc.w += v.w;
    }

    __shared__ float4 red[256];
    red[tid] = acc;
    __syncthreads();
    if (t < 64) {
        float4 b = red[tid + 64];
        red[tid].x += b.x; red[tid].y += b.y; red[tid].z += b.z; red[tid].w += b.w;
    }
    __syncthreads();
    if (t < 32) {
        float4 b = red[tid + 32];
        red[tid].x += b.x; red[tid].y += b.y; red[tid].z += b.z; red[tid].w += b.w;
    }
    __syncthreads();
    if (t < 16) {
        float4 a = red[tid], b = red[tid + 16];
        float4 g;
        g.x = (a.x + b.x) * (1.f / 32.f);
        g.y = (a.y + b.y) * (1.f / 32.f);
        g.z = (a.z + b.z) * (1.f / 32.f);
        g.w = (a.w + b.w) * (1.f / 32.f);
        ((float4*)(d_g_raw + (size_t)n * MEME_DIM))[t] = g;

        float s = g.x + g.y + g.z + g.w;
        float q = g.x * g.x + g.y * g.y + g.z * g.z + g.w * g.w;
#pragma unroll
        for (int o = 8; o > 0; o >>= 1) {
            s += __shfl_down_sync(0xffffu, s, o, 16);
            q += __shfl_down_sync(0xffffu, q, o, 16);
        }
        if (t == 0) d_partials[n] = make_float2(s, q);
    }
}

// ---------------------------------------------------------------------------
// Kernel 2: reduce partials -> global mean / inv_std (ddof=1), deterministic
// ---------------------------------------------------------------------------
__global__ __launch_bounds__(256) void stats_kernel()
{
    __shared__ double ssum[256], ssq[256];
    const int tid = threadIdx.x;
    double s = 0.0, q = 0.0;
    for (int i = tid; i < NUM_NODES; i += 256) {
        float2 p = d_partials[i];
        s += (double)p.x;
        q += (double)p.y;
    }
    ssum[tid] = s; ssq[tid] = q;
    __syncthreads();
    for (int st = 128; st > 0; st >>= 1) {
        if (tid < st) { ssum[tid] += ssum[tid + st]; ssq[tid] += ssq[tid + st]; }
        __syncthreads();
    }
    if (tid == 0) {
        const double N = (double)G_TOT;
        double mean = ssum[0] / N;
        double var  = (ssq[0] - ssum[0] * ssum[0] / N) / (N - 1.0);
        d_stats[0] = (float)mean;
        d_stats[1] = (float)(1.0 / sqrt(var));
    }
}

// ---------------------------------------------------------------------------
// Kernel 3: fused remix. 512 threads, persistent, TMA triple-buffered,
// 2 barriers per tile, single-warp stats, width-8 output reduction.
// ---------------------------------------------------------------------------
__global__ __launch_bounds__(RTHREADS, 1) void remix_kernel(
    const float* __restrict__ vocab,       // [8192, 64, 256]
    const float* __restrict__ raw_sc,      // [1]
    const float* __restrict__ raw_sh,      // [1]
    float*       __restrict__ out)         // [8192, 64]
{
    extern __shared__ __align__(128) float smem[];
    float*  bufs = smem;                                  // 3 * 16384 floats
    float4* pd4  = (float4*)(smem + NBUF * TILE_FLOATS);  // 512 float4 (8KB)
    float4* fs4  = (float4*)(smem + NBUF * TILE_FLOATS + 2048); // 64 float4
    __shared__ __align__(8) unsigned long long mbar_s[NBUF];

    const int tid  = threadIdx.x;
    const int lane = tid & 31, w = tid >> 5;
    const int c4   = tid & 63;     // float4 column group for dot phase
    const int ch   = tid >> 6;     // e-chunk 0..7
    const int eo   = tid >> 3;     // output e (0..63) for phase E
    const int p8   = tid & 7;      // sub-slot within e

    unsigned mb[NBUF];
#pragma unroll
    for (int i = 0; i < NBUF; i++) mb[i] = smem_u32(&mbar_s[i]);
    unsigned sb[NBUF];
#pragma unroll
    for (int i = 0; i < NBUF; i++) sb[i] = smem_u32(bufs + i * TILE_FLOATS);

    if (tid == 0) {
#pragma unroll
        for (int i = 0; i < NBUF; i++) mbar_init(mb[i], 1);
        asm volatile("fence.proxy.async.shared::cta;" ::: "memory");
    }
    __syncthreads();

    const float sc     = __expf(__ldg(raw_sc));
    const float inv_sc = __fdividef(1.f, sc);
    const float lnsh   = __ldg(raw_sh);
    const float mean   = d_stats[0], istd = d_stats[1];

    const int n0 = blockIdx.x;
    if (tid == 0) {
#pragma unroll
        for (int i = 0; i < 2; i++) {
            const int nn = n0 + i * GRID_P;
            if (nn < NUM_NODES) {
                mbar_expect_tx(mb[i], TILE_BYTES);
                bulk_ldgsts(sb[i], vocab + (size_t)nn * TILE_FLOATS, TILE_BYTES, mb[i]);
            }
        }
    }

    int it = 0, slot = 0, phase = 0;
    for (int n = n0; n < NUM_NODES; n += GRID_P, ++it) {
        const float4* vs4 = (const float4*)(bufs + slot * TILE_FLOATS);

        // g row -> registers (broadcast LDG, overlaps the mbar wait)
        const float4* g4 = (const float4*)(d_g_raw + (size_t)n * MEME_DIM);
        float4 ga = __ldg(g4 + ch * 2);
        float4 gb = __ldg(g4 + ch * 2 + 1);
        float gr[8];
        gr[0] = (ga.x - mean) * istd; gr[1] = (ga.y - mean) * istd;
        gr[2] = (ga.z - mean) * istd; gr[3] = (ga.w - mean) * istd;
        gr[4] = (gb.x - mean) * istd; gr[5] = (gb.y - mean) * istd;
        gr[6] = (gb.z - mean) * istd; gr[7] = (gb.w - mean) * istd;

        mbar_wait(mb[slot], phase);

        // ---- phase B: dot partials. thread: column group c4, e-chunk ch ----
        {
            float4 a = make_float4(0.f, 0.f, 0.f, 0.f);
#pragma unroll
            for (int j = 0; j < 8; j++) {
                const float4 vv = vs4[(ch * 8 + j) * 64 + c4];
                const float ge = gr[j];
                a.x = fmaf(ge, vv.x, a.x);
                a.y = fmaf(ge, vv.y, a.y);
                a.z = fmaf(ge, vv.z, a.z);
                a.w = fmaf(ge, vv.w, a.w);
            }
            pd4[ch * 64 + c4] = a;
        }
        __syncthreads();                                   // barrier 1

        // prefetch tile it+2 (warp 1; safe: all threads finished iter it-1)
        {
            const int nn = n + 2 * GRID_P;
            if (nn < NUM_NODES && tid == 32) {
                int ps = slot + 2; if (ps >= NBUF) ps -= NBUF;
                mbar_expect_tx(mb[ps], TILE_BYTES);
                bulk_ldgsts(sb[ps], vocab + (size_t)nn * TILE_FLOATS, TILE_BYTES, mb[ps]);
            }
        }

        // ---- phase C+D: stats + fractions, entirely in warp 0 ----
        if (w == 0) {
            float4 dva = make_float4(0.f, 0.f, 0.f, 0.f);
            float4 dvb = make_float4(0.f, 0.f, 0.f, 0.f);
#pragma unroll
            for (int k = 0; k < 8; k++) {
                float4 a = pd4[k * 64 + lane];
                float4 b = pd4[k * 64 + lane + 32];
                dva.x += a.x; dva.y += a.y; dva.z += a.z; dva.w += a.w;
                dvb.x += b.x; dvb.y += b.y; dvb.z += b.z; dvb.w += b.w;
            }
            float s = dva.x + dva.y + dva.z + dva.w + dvb.x + dvb.y + dvb.z + dvb.w;
            float q = dva.x * dva.x + dva.y * dva.y + dva.z * dva.z + dva.w * dva.w
                    + dvb.x * dvb.x + dvb.y * dvb.y + dvb.z * dvb.z + dvb.w * dvb.w;
#pragma unroll
            for (int o = 16; o > 0; o >>= 1) {
                s += __shfl_down_sync(0xffffffffu, s, o);
                q += __shfl_down_sync(0xffffffffu, q, o);
            }
            s = __shfl_sync(0xffffffffu, s, 0);
            q = __shfl_sync(0xffffffffu, q, 0);

            const float m = s * (1.f / 256.f);
            float var = (q - s * s * (1.f / 256.f)) * (1.f / 255.f);
            var = fmaxf(var, 0.f);
            const float inv_sd = __fdividef(1.f, sqrtf(var) + 0.001f);

            float4 pa, pb;
            pa.x = __expf(fast_tanh((dva.x - m) * inv_sd * inv_sc) * sc * lnsh);
            pa.y = __expf(fast_tanh((dva.y - m) * inv_sd * inv_sc) * sc * lnsh);
            pa.z = __expf(fast_tanh((dva.z - m) * inv_sd * inv_sc) * sc * lnsh);
            pa.w = __expf(fast_tanh((dva.w - m) * inv_sd * inv_sc) * sc * lnsh);
            pb.x = __expf(fast_tanh((dvb.x - m) * inv_sd * inv_sc) * sc * lnsh);
            pb.y = __expf(fast_tanh((dvb.y - m) * inv_sd * inv_sc) * sc * lnsh);
            pb.z = __expf(fast_tanh((dvb.z - m) * inv_sd * inv_sc) * sc * lnsh);
            pb.w = __expf(fast_tanh((dvb.w - m) * inv_sd * inv_sc) * sc * lnsh);

            float ps = pa.x + pa.y + pa.z + pa.w + pb.x + pb.y + pb.z + pb.w;
#pragma unroll
            for (int o = 16; o > 0; o >>= 1)
                ps += __shfl_down_sync(0xffffffffu, ps, o);
            ps = __shfl_sync(0xffffffffu, ps, 0);
            const float inv_psum = __fdividef(1.f, ps + 0.001f);

            float4 fa, fb;
            fa.x = pa.x * inv_psum; fa.y = pa.y * inv_psum;
            fa.z = pa.z * inv_psum; fa.w = pa.w * inv_psum;
            fb.x = pb.x * inv_psum; fb.y = pb.y * inv_psum;
            fb.z = pb.z * inv_psum; fb.w = pb.w * inv_psum;
            fs4[lane] = fa;
            fs4[lane + 32] = fb;
        }
        __syncthreads();                                   // barrier 2

        // ---- phase E: out[e] via 8 threads per e, width-8 reduction ----
        {
            float a = 0.f;
#pragma unroll
            for (int k = 0; k < 8; k++) {
                const float4 vv = vs4[eo * 64 + p8 + 8 * k];
                const float4 ff = fs4[p8 + 8 * k];
                a = fmaf(vv.x, ff.x, a);
                a = fmaf(vv.y, ff.y, a);
                a = fmaf(vv.z, ff.z, a);
                a = fmaf(vv.w, ff.w, a);
            }
            a += __shfl_down_sync(0xffffffffu, a, 4, 8);
            a += __shfl_down_sync(0xffffffffu, a, 2, 8);
            a += __shfl_down_sync(0xffffffffu, a, 1, 8);
            if (p8 == 0) out[(size_t)n * MEME_DIM + eo] = a;
        }
        // no end barrier needed: next iter's barrier 1 orders buffer reuse

        if (++slot == NBUF) { slot = 0; phase ^= 1; }
    }
}

// ---------------------------------------------------------------------------
extern "C" void kernel_launch(void* const* d_in, const int* in_sizes, int n_in,
                              void* d_out, int out_size)
{
    const float* x      = (const float*)d_in[0];   // [2048, 64]
    const float* memes  = (const float*)d_in[1];   // [8192, 64]
    const int*   idx    = (const int*)  d_in[2];   // [8192, 32]
    const float* vocab  = (const float*)d_in[3];   // [8192, 64, 256]
    const float* raw_sc = (const float*)d_in[4];   // [1]
    const float* raw_sh = (const float*)d_in[5];   // [1]
    float* out = (float*)d_out;

    const int smem_bytes = (NBUF * TILE_FLOATS + 2048 + 256) * sizeof(float); // 205824
    static int attr_set = 0;
    if (!attr_set) {
        cudaFuncSetAttribute(remix_kernel, cudaFuncAttributeMaxDynamicSharedMemorySize, smem_bytes);
        attr_set = 1;
    }

    gather_kernel<<<NUM_NODES / 2, 256>>>(x, memes, idx);
    stats_kernel<<<1, 256>>>();
    remix_kernel<<<GRID_P, RTHREADS, smem_bytes>>>(vocab, raw_sc, raw_sh, out);
}

// round 8
// speedup vs baseline: 1.2612x; 1.2612x over previous
#include <cuda_runtime.h>
#include <math.h>

#define NUM_NODES   8192
#define MEME_DIM    64
#define VISION      2048
#define K_IN        32
#define VOCAB_N     256
#define G_TOT       (NUM_NODES * MEME_DIM)
#define TILE_F4     4096                         // float4s per tile (64*256/4)
#define GRID_P      148                          // persistent CTAs (1/SM)
#define RTHREADS    512

// Scratch (device globals; no allocation allowed)
__device__ float  d_g_raw[G_TOT];
__device__ float2 d_partials[NUM_NODES];
__device__ float  d_stats[2];  // [0]=mean, [1]=inv_std

__device__ __forceinline__ float fast_tanh(float x) {
    float r;
    asm("tanh.approx.f32 %0, %1;" : "=f"(r) : "f"(x));
    return r;
}

// ---------------------------------------------------------------------------
// Kernel 1: gather + mean. 2 nodes per 256-thread block; 4-way MLP per thread.
// ---------------------------------------------------------------------------
__global__ __launch_bounds__(256) void gather_kernel(
    const float* __restrict__ x,          // [2048, 64]
    const float* __restrict__ memes,      // [8192, 64]
    const int*   __restrict__ idx)        // [8192, 32]
{
    const int tid  = threadIdx.x;
    const int half = tid >> 7;
    const int t    = tid & 127;
    const int n    = blockIdx.x * 2 + half;
    const int f4   = t & 15;
    const int kb   = t >> 4;

    const int* ri = idx + (size_t)n * K_IN;

    float4 acc = make_float4(0.f, 0.f, 0.f, 0.f);
#pragma unroll
    for (int j = 0; j < 4; j++) {
        int r = __ldg(ri + kb + 8 * j);
        const float4* src = (r < VISION)
            ? (const float4*)(x + (size_t)r * MEME_DIM)
            : (const float4*)(memes + (size_t)(r - VISION) * MEME_DIM);
        float4 v = __ldg(src + f4);
        acc.x += v.x; acc.y += v.y; acc.z += v.z; acc.w += v.w;
    }

    __shared__ float4 red[256];
    red[tid] = acc;
    __syncthreads();
    if (t < 64) {
        float4 b = red[tid + 64];
        red[tid].x += b.x; red[tid].y += b.y; red[tid].z += b.z; red[tid].w += b.w;
    }
    __syncthreads();
    if (t < 32) {
        float4 b = red[tid + 32];
        red[tid].x += b.x; red[tid].y += b.y; red[tid].z += b.z; red[tid].w += b.w;
    }
    __syncthreads();
    if (t < 16) {
        float4 a = red[tid], b = red[tid + 16];
        float4 g;
        g.x = (a.x + b.x) * (1.f / 32.f);
        g.y = (a.y + b.y) * (1.f / 32.f);
        g.z = (a.z + b.z) * (1.f / 32.f);
        g.w = (a.w + b.w) * (1.f / 32.f);
        ((float4*)(d_g_raw + (size_t)n * MEME_DIM))[t] = g;

        float s = g.x + g.y + g.z + g.w;
        float q = g.x * g.x + g.y * g.y + g.z * g.z + g.w * g.w;
#pragma unroll
        for (int o = 8; o > 0; o >>= 1) {
            s += __shfl_down_sync(0xffffu, s, o, 16);
            q += __shfl_down_sync(0xffffu, q, o, 16);
        }
        if (t == 0) d_partials[n] = make_float2(s, q);
    }
}

// ---------------------------------------------------------------------------
// Kernel 2: reduce partials -> global mean / inv_std (ddof=1), deterministic
// ---------------------------------------------------------------------------
__global__ __launch_bounds__(256) void stats_kernel()
{
    __shared__ double ssum[256], ssq[256];
    const int tid = threadIdx.x;
    double s = 0.0, q = 0.0;
    for (int i = tid; i < NUM_NODES; i += 256) {
        float2 p = d_partials[i];
        s += (double)p.x;
        q += (double)p.y;
    }
    ssum[tid] = s; ssq[tid] = q;
    __syncthreads();
    for (int st = 128; st > 0; st >>= 1) {
        if (tid < st) { ssum[tid] += ssum[tid + st]; ssq[tid] += ssq[tid + st]; }
        __syncthreads();
    }
    if (tid == 0) {
        const double N = (double)G_TOT;
        double mean = ssum[0] / N;
        double var  = (ssq[0] - ssum[0] * ssum[0] / N) / (N - 1.0);
        d_stats[0] = (float)mean;
        d_stats[1] = (float)(1.0 / sqrt(var));
    }
}

// ---------------------------------------------------------------------------
// Kernel 3: fused remix, register-resident vocab (no smem/TMA on the 512MB
// stream). Persistent 148 CTAs x 512 threads, software-pipelined LDG.
// Thread (c4 = tid&63, ch = tid>>6) owns cols 4*c4..4*c4+3 of e = ch*8..ch*8+7.
// ---------------------------------------------------------------------------
struct RemixSmem {
    float4 pd4[512];       // 8KB  dot partials
    float  po[64 * 64];    // 16KB out partials [e][c4]
    float4 fs4[64];        // 1KB  fractions
};

__global__ __launch_bounds__(RTHREADS, 1) void remix_kernel(
    const float* __restrict__ vocab,       // [8192, 64, 256]
    const float* __restrict__ raw_sc,      // [1]
    const float* __restrict__ raw_sh,      // [1]
    float*       __restrict__ out)         // [8192, 64]
{
    __shared__ RemixSmem sm;

    const int tid  = threadIdx.x;
    const int lane = tid & 31, w = tid >> 5;
    const int c4   = tid & 63;
    const int ch   = tid >> 6;

    const float sc     = __expf(__ldg(raw_sc));
    const float inv_sc = __fdividef(1.f, sc);
    const float lnsh   = __ldg(raw_sh);
    const float mean   = d_stats[0], istd = d_stats[1];

    const float4* v4 = (const float4*)vocab;

    // -------- per-tile step (expects vocab tile + raw g in registers) -------
    auto step = [&](int n, float4 (&cur)[8], float4& ga, float4& gb,
                    float4 (&nxt)[8], float4& gna, float4& gnb) {
        // standardize g
        float gr[8];
        gr[0] = (ga.x - mean) * istd; gr[1] = (ga.y - mean) * istd;
        gr[2] = (ga.z - mean) * istd; gr[3] = (ga.w - mean) * istd;
        gr[4] = (gb.x - mean) * istd; gr[5] = (gb.y - mean) * istd;
        gr[6] = (gb.z - mean) * istd; gr[7] = (gb.w - mean) * istd;

        // ---- phase B: dot partials over this thread's 8 e's ----
        float4 a = make_float4(0.f, 0.f, 0.f, 0.f);
#pragma unroll
        for (int j = 0; j < 8; j++) {
            a.x = fmaf(gr[j], cur[j].x, a.x);
            a.y = fmaf(gr[j], cur[j].y, a.y);
            a.z = fmaf(gr[j], cur[j].z, a.z);
            a.w = fmaf(gr[j], cur[j].w, a.w);
        }
        sm.pd4[ch * 64 + c4] = a;
        __syncthreads();                                   // barrier 1

        // ---- prefetch tile n+GRID_P into nxt (overlaps stats) ----
        const int nn = n + GRID_P;
        if (nn < NUM_NODES) {
            const float4* src = v4 + (size_t)nn * TILE_F4 + c4;
#pragma unroll
            for (int j = 0; j < 8; j++)
                nxt[j] = __ldcs(src + (ch * 8 + j) * 64);
            const float4* g4 = (const float4*)(d_g_raw + (size_t)nn * MEME_DIM);
            gna = __ldg(g4 + ch * 2);
            gnb = __ldg(g4 + ch * 2 + 1);
        }

        // ---- stats + fractions: warp 0 ----
        if (w == 0) {
            float4 dva = make_float4(0.f, 0.f, 0.f, 0.f);
            float4 dvb = make_float4(0.f, 0.f, 0.f, 0.f);
#pragma unroll
            for (int k = 0; k < 8; k++) {
                float4 pa = sm.pd4[k * 64 + lane];
                float4 pb = sm.pd4[k * 64 + lane + 32];
                dva.x += pa.x; dva.y += pa.y; dva.z += pa.z; dva.w += pa.w;
                dvb.x += pb.x; dvb.y += pb.y; dvb.z += pb.z; dvb.w += pb.w;
            }
            float s = dva.x + dva.y + dva.z + dva.w + dvb.x + dvb.y + dvb.z + dvb.w;
            float q = dva.x * dva.x + dva.y * dva.y + dva.z * dva.z + dva.w * dva.w
                    + dvb.x * dvb.x + dvb.y * dvb.y + dvb.z * dvb.z + dvb.w * dvb.w;
#pragma unroll
            for (int o = 16; o > 0; o >>= 1) {
                s += __shfl_down_sync(0xffffffffu, s, o);
                q += __shfl_down_sync(0xffffffffu, q, o);
            }
            s = __shfl_sync(0xffffffffu, s, 0);
            q = __shfl_sync(0xffffffffu, q, 0);

            const float m = s * (1.f / 256.f);
            float var = (q - s * s * (1.f / 256.f)) * (1.f / 255.f);
            var = fmaxf(var, 0.f);
            const float inv_sd = __fdividef(1.f, sqrtf(var) + 0.001f);

            float4 pa, pb;
            pa.x = __expf(fast_tanh((dva.x - m) * inv_sd * inv_sc) * sc * lnsh);
            pa.y = __expf(fast_tanh((dva.y - m) * inv_sd * inv_sc) * sc * lnsh);
            pa.z = __expf(fast_tanh((dva.z - m) * inv_sd * inv_sc) * sc * lnsh);
            pa.w = __expf(fast_tanh((dva.w - m) * inv_sd * inv_sc) * sc * lnsh);
            pb.x = __expf(fast_tanh((dvb.x - m) * inv_sd * inv_sc) * sc * lnsh);
            pb.y = __expf(fast_tanh((dvb.y - m) * inv_sd * inv_sc) * sc * lnsh);
            pb.z = __expf(fast_tanh((dvb.z - m) * inv_sd * inv_sc) * sc * lnsh);
            pb.w = __expf(fast_tanh((dvb.w - m) * inv_sd * inv_sc) * sc * lnsh);

            float ps = pa.x + pa.y + pa.z + pa.w + pb.x + pb.y + pb.z + pb.w;
#pragma unroll
            for (int o = 16; o > 0; o >>= 1)
                ps += __shfl_down_sync(0xffffffffu, ps, o);
            ps = __shfl_sync(0xffffffffu, ps, 0);
            const float inv_psum = __fdividef(1.f, ps + 0.001f);

            float4 fa, fb;
            fa.x = pa.x * inv_psum; fa.y = pa.y * inv_psum;
            fa.z = pa.z * inv_psum; fa.w = pa.w * inv_psum;
            fb.x = pb.x * inv_psum; fb.y = pb.y * inv_psum;
            fb.z = pb.z * inv_psum; fb.w = pb.w * inv_psum;
            sm.fs4[lane] = fa;
            sm.fs4[lane + 32] = fb;
        }
        __syncthreads();                                   // barrier 2

        // ---- phase E: out partials from register-resident vocab ----
        {
            const float4 f = sm.fs4[c4];
#pragma unroll
            for (int j = 0; j < 8; j++) {
                float p = cur[j].x * f.x + cur[j].y * f.y
                        + cur[j].z * f.z + cur[j].w * f.w;
                sm.po[(ch * 8 + j) * 64 + c4] = p;
            }
        }
        __syncthreads();                                   // barrier 3

        // ---- final reduce: 8 threads per e ----
        {
            const int eo = tid >> 3, p8 = tid & 7;
            const float4* pr = (const float4*)(sm.po + eo * 64 + p8 * 8);
            const float4 r0 = pr[0], r1 = pr[1];
            float s = r0.x + r0.y + r0.z + r0.w + r1.x + r1.y + r1.z + r1.w;
            s += __shfl_down_sync(0xffffffffu, s, 4, 8);
            s += __shfl_down_sync(0xffffffffu, s, 2, 8);
            s += __shfl_down_sync(0xffffffffu, s, 1, 8);
            if (p8 == 0) out[(size_t)n * MEME_DIM + eo] = s;
        }
        // no end barrier: next step's smem writes are ordered by its barriers
    };

    // -------- preload tile n0 --------
    const int n0 = blockIdx.x;
    float4 bufA[8], bufB[8];
    float4 gAa, gAb, gBa, gBb;
    {
        const float4* src = v4 + (size_t)n0 * TILE_F4 + c4;
#pragma unroll
        for (int j = 0; j < 8; j++)
            bufA[j] = __ldcs(src + (ch * 8 + j) * 64);
        const float4* g4 = (const float4*)(d_g_raw + (size_t)n0 * MEME_DIM);
        gAa = __ldg(g4 + ch * 2);
        gAb = __ldg(g4 + ch * 2 + 1);
    }

    int n = n0;
    while (true) {
        step(n, bufA, gAa, gAb, bufB, gBa, gBb);           // prefetches n+GRID_P
        n += GRID_P;
        if (n >= NUM_NODES) break;
        step(n, bufB, gBa, gBb, bufA, gAa, gAb);           // prefetches n+GRID_P
        n += GRID_P;
        if (n >= NUM_NODES) break;
    }
}

// ---------------------------------------------------------------------------
extern "C" void kernel_launch(void* const* d_in, const int* in_sizes, int n_in,
                              void* d_out, int out_size)
{
    const float* x      = (const float*)d_in[0];   // [2048, 64]
    const float* memes  = (const float*)d_in[1];   // [8192, 64]
    const int*   idx    = (const int*)  d_in[2];   // [8192, 32]
    const float* vocab  = (const float*)d_in[3];   // [8192, 64, 256]
    const float* raw_sc = (const float*)d_in[4];   // [1]
    const float* raw_sh = (const float*)d_in[5];   // [1]
    float* out = (float*)d_out;

    gather_kernel<<<NUM_NODES / 2, 256>>>(x, memes, idx);
    stats_kernel<<<1, 256>>>();
    remix_kernel<<<GRID_P, RTHREADS>>>(vocab, raw_sc, raw_sh, out);
}

// round 9
// speedup vs baseline: 1.2653x; 1.0032x over previous
#include <cuda_runtime.h>
#include <math.h>

#define NUM_NODES   8192
#define MEME_DIM    64
#define VISION      2048
#define K_IN        32
#define VOCAB_N     256
#define G_TOT       (NUM_NODES * MEME_DIM)
#define TILE_F4     4096                         // float4s per tile (64*256/4)
#define GRID_P      148                          // persistent CTAs (1/SM)
#define RTHREADS    512

// Scratch (device globals; no allocation allowed)
__device__ float  d_g_raw[G_TOT];
__device__ float2 d_partials[NUM_NODES];
__device__ float  d_stats[2];  // [0]=mean, [1]=inv_std

__device__ __forceinline__ float fast_tanh(float x) {
    float r;
    asm("tanh.approx.f32 %0, %1;" : "=f"(r) : "f"(x));
    return r;
}

// ---------------------------------------------------------------------------
// Kernel 1: gather + mean. 2 nodes per 256-thread block; 4-way MLP per thread.
// ---------------------------------------------------------------------------
__global__ __launch_bounds__(256) void gather_kernel(
    const float* __restrict__ x,          // [2048, 64]
    const float* __restrict__ memes,      // [8192, 64]
    const int*   __restrict__ idx)        // [8192, 32]
{
    const int tid  = threadIdx.x;
    const int half = tid >> 7;
    const int t    = tid & 127;
    const int n    = blockIdx.x * 2 + half;
    const int f4   = t & 15;
    const int kb   = t >> 4;

    const int* ri = idx + (size_t)n * K_IN;

    float4 acc = make_float4(0.f, 0.f, 0.f, 0.f);
#pragma unroll
    for (int j = 0; j < 4; j++) {
        int r = __ldg(ri + kb + 8 * j);
        const float4* src = (r < VISION)
            ? (const float4*)(x + (size_t)r * MEME_DIM)
            : (const float4*)(memes + (size_t)(r - VISION) * MEME_DIM);
        float4 v = __ldg(src + f4);
        acc.x += v.x; acc.y += v.y; acc.z += v.z; acc.w += v.w;
    }

    __shared__ float4 red[256];
    red[tid] = acc;
    __syncthreads();
    if (t < 64) {
        float4 b = red[tid + 64];
        red[tid].x += b.x; red[tid].y += b.y; red[tid].z += b.z; red[tid].w += b.w;
    }
    __syncthreads();
    if (t < 32) {
        float4 b = red[tid + 32];
        red[tid].x += b.x; red[tid].y += b.y; red[tid].z += b.z; red[tid].w += b.w;
    }
    __syncthreads();
    if (t < 16) {
        float4 a = red[tid], b = red[tid + 16];
        float4 g;
        g.x = (a.x + b.x) * (1.f / 32.f);
        g.y = (a.y + b.y) * (1.f / 32.f);
        g.z = (a.z + b.z) * (1.f / 32.f);
        g.w = (a.w + b.w) * (1.f / 32.f);
        ((float4*)(d_g_raw + (size_t)n * MEME_DIM))[t] = g;

        float s = g.x + g.y + g.z + g.w;
        float q = g.x * g.x + g.y * g.y + g.z * g.z + g.w * g.w;
#pragma unroll
        for (int o = 8; o > 0; o >>= 1) {
            s += __shfl_down_sync(0xffffu, s, o, 16);
            q += __shfl_down_sync(0xffffu, q, o, 16);
        }
        if (t == 0) d_partials[n] = make_float2(s, q);
    }
}

// ---------------------------------------------------------------------------
// Kernel 2: reduce partials -> global mean / inv_std (ddof=1), deterministic
// ---------------------------------------------------------------------------
__global__ __launch_bounds__(256) void stats_kernel()
{
    __shared__ double ssum[256], ssq[256];
    const int tid = threadIdx.x;
    double s = 0.0, q = 0.0;
    for (int i = tid; i < NUM_NODES; i += 256) {
        float2 p = d_partials[i];
        s += (double)p.x;
        q += (double)p.y;
    }
    ssum[tid] = s; ssq[tid] = q;
    __syncthreads();
    for (int st = 128; st > 0; st >>= 1) {
        if (tid < st) { ssum[tid] += ssum[tid + st]; ssq[tid] += ssq[tid + st]; }
        __syncthreads();
    }
    if (tid == 0) {
        const double N = (double)G_TOT;
        double mean = ssum[0] / N;
        double var  = (ssq[0] - ssum[0] * ssum[0] / N) / (N - 1.0);
        d_stats[0] = (float)mean;
        d_stats[1] = (float)(1.0 / sqrt(var));
    }
}

// ---------------------------------------------------------------------------
// Kernel 3: fused remix, register-resident vocab (no smem/TMA on the 512MB
// stream). Persistent 148 CTAs x 512 threads, software-pipelined LDG.
// Thread (c4 = tid&63, ch = tid>>6) owns cols 4*c4..4*c4+3 of e = ch*8..ch*8+7.
// ---------------------------------------------------------------------------
struct RemixSmem {
    float4 pd4[512];       // 8KB  dot partials
    float  po[64 * 64];    // 16KB out partials [e][c4]
    float4 fs4[64];        // 1KB  fractions
};

__global__ __launch_bounds__(RTHREADS, 1) void remix_kernel(
    const float* __restrict__ vocab,       // [8192, 64, 256]
    const float* __restrict__ raw_sc,      // [1]
    const float* __restrict__ raw_sh,      // [1]
    float*       __restrict__ out)         // [8192, 64]
{
    __shared__ RemixSmem sm;

    const int tid  = threadIdx.x;
    const int lane = tid & 31, w = tid >> 5;
    const int c4   = tid & 63;
    const int ch   = tid >> 6;

    const float sc     = __expf(__ldg(raw_sc));
    const float inv_sc = __fdividef(1.f, sc);
    const float lnsh   = __ldg(raw_sh);
    const float mean   = d_stats[0], istd = d_stats[1];

    const float4* v4 = (const float4*)vocab;

    // -------- per-tile step (expects vocab tile + raw g in registers) -------
    auto step = [&](int n, float4 (&cur)[8], float4& ga, float4& gb,
                    float4 (&nxt)[8], float4& gna, float4& gnb) {
        // standardize g
        float gr[8];
        gr[0] = (ga.x - mean) * istd; gr[1] = (ga.y - mean) * istd;
        gr[2] = (ga.z - mean) * istd; gr[3] = (ga.w - mean) * istd;
        gr[4] = (gb.x - mean) * istd; gr[5] = (gb.y - mean) * istd;
        gr[6] = (gb.z - mean) * istd; gr[7] = (gb.w - mean) * istd;

        // ---- phase B: dot partials over this thread's 8 e's ----
        float4 a = make_float4(0.f, 0.f, 0.f, 0.f);
#pragma unroll
        for (int j = 0; j < 8; j++) {
            a.x = fmaf(gr[j], cur[j].x, a.x);
            a.y = fmaf(gr[j], cur[j].y, a.y);
            a.z = fmaf(gr[j], cur[j].z, a.z);
            a.w = fmaf(gr[j], cur[j].w, a.w);
        }
        sm.pd4[ch * 64 + c4] = a;
        __syncthreads();                                   // barrier 1

        // ---- prefetch tile n+GRID_P into nxt (overlaps stats) ----
        const int nn = n + GRID_P;
        if (nn < NUM_NODES) {
            const float4* src = v4 + (size_t)nn * TILE_F4 + c4;
#pragma unroll
            for (int j = 0; j < 8; j++)
                nxt[j] = __ldcs(src + (ch * 8 + j) * 64);
            const float4* g4 = (const float4*)(d_g_raw + (size_t)nn * MEME_DIM);
            gna = __ldg(g4 + ch * 2);
            gnb = __ldg(g4 + ch * 2 + 1);
        }

        // ---- stats + fractions: warp 0 ----
        if (w == 0) {
            float4 dva = make_float4(0.f, 0.f, 0.f, 0.f);
            float4 dvb = make_float4(0.f, 0.f, 0.f, 0.f);
#pragma unroll
            for (int k = 0; k < 8; k++) {
                float4 pa = sm.pd4[k * 64 + lane];
                float4 pb = sm.pd4[k * 64 + lane + 32];
                dva.x += pa.x; dva.y += pa.y; dva.z += pa.z; dva.w += pa.w;
                dvb.x += pb.x; dvb.y += pb.y; dvb.z += pb.z; dvb.w += pb.w;
            }
            float s = dva.x + dva.y + dva.z + dva.w + dvb.x + dvb.y + dvb.z + dvb.w;
            float q = dva.x * dva.x + dva.y * dva.y + dva.z * dva.z + dva.w * dva.w
                    + dvb.x * dvb.x + dvb.y * dvb.y + dvb.z * dvb.z + dvb.w * dvb.w;
#pragma unroll
            for (int o = 16; o > 0; o >>= 1) {
                s += __shfl_down_sync(0xffffffffu, s, o);
                q += __shfl_down_sync(0xffffffffu, q, o);
            }
            s = __shfl_sync(0xffffffffu, s, 0);
            q = __shfl_sync(0xffffffffu, q, 0);

            const float m = s * (1.f / 256.f);
            float var = (q - s * s * (1.f / 256.f)) * (1.f / 255.f);
            var = fmaxf(var, 0.f);
            const float inv_sd = __fdividef(1.f, sqrtf(var) + 0.001f);

            float4 pa, pb;
            pa.x = __expf(fast_tanh((dva.x - m) * inv_sd * inv_sc) * sc * lnsh);
            pa.y = __expf(fast_tanh((dva.y - m) * inv_sd * inv_sc) * sc * lnsh);
            pa.z = __expf(fast_tanh((dva.z - m) * inv_sd * inv_sc) * sc * lnsh);
            pa.w = __expf(fast_tanh((dva.w - m) * inv_sd * inv_sc) * sc * lnsh);
            pb.x = __expf(fast_tanh((dvb.x - m) * inv_sd * inv_sc) * sc * lnsh);
            pb.y = __expf(fast_tanh((dvb.y - m) * inv_sd * inv_sc) * sc * lnsh);
            pb.z = __expf(fast_tanh((dvb.z - m) * inv_sd * inv_sc) * sc * lnsh);
            pb.w = __expf(fast_tanh((dvb.w - m) * inv_sd * inv_sc) * sc * lnsh);

            float ps = pa.x + pa.y + pa.z + pa.w + pb.x + pb.y + pb.z + pb.w;
#pragma unroll
            for (int o = 16; o > 0; o >>= 1)
                ps += __shfl_down_sync(0xffffffffu, ps, o);
            ps = __shfl_sync(0xffffffffu, ps, 0);
            const float inv_psum = __fdividef(1.f, ps + 0.001f);

            float4 fa, fb;
            fa.x = pa.x * inv_psum; fa.y = pa.y * inv_psum;
            fa.z = pa.z * inv_psum; fa.w = pa.w * inv_psum;
            fb.x = pb.x * inv_psum; fb.y = pb.y * inv_psum;
            fb.z = pb.z * inv_psum; fb.w = pb.w * inv_psum;
            sm.fs4[lane] = fa;
            sm.fs4[lane + 32] = fb;
        }
        __syncthreads();                                   // barrier 2

        // ---- phase E: out partials from register-resident vocab ----
        {
            const float4 f = sm.fs4[c4];
#pragma unroll
            for (int j = 0; j < 8; j++) {
                float p = cur[j].x * f.x + cur[j].y * f.y
                        + cur[j].z * f.z + cur[j].w * f.w;
                sm.po[(ch * 8 + j) * 64 + c4] = p;
            }
        }
        __syncthreads();                                   // barrier 3

        // ---- final reduce: 8 threads per e ----
        {
            const int eo = tid >> 3, p8 = tid & 7;
            const float4* pr = (const float4*)(sm.po + eo * 64 + p8 * 8);
            const float4 r0 = pr[0], r1 = pr[1];
            float s = r0.x + r0.y + r0.z + r0.w + r1.x + r1.y + r1.z + r1.w;
            s += __shfl_down_sync(0xffffffffu, s, 4, 8);
            s += __shfl_down_sync(0xffffffffu, s, 2, 8);
            s += __shfl_down_sync(0xffffffffu, s, 1, 8);
            if (p8 == 0) out[(size_t)n * MEME_DIM + eo] = s;
        }
        // no end barrier: next step's smem writes are ordered by its barriers
    };

    // -------- preload tile n0 --------
    const int n0 = blockIdx.x;
    float4 bufA[8], bufB[8];
    float4 gAa, gAb, gBa, gBb;
    {
        const float4* src = v4 + (size_t)n0 * TILE_F4 + c4;
#pragma unroll
        for (int j = 0; j < 8; j++)
            bufA[j] = __ldcs(src + (ch * 8 + j) * 64);
        const float4* g4 = (const float4*)(d_g_raw + (size_t)n0 * MEME_DIM);
        gAa = __ldg(g4 + ch * 2);
        gAb = __ldg(g4 + ch * 2 + 1);
    }

    int n = n0;
    while (true) {
        step(n, bufA, gAa, gAb, bufB, gBa, gBb);           // prefetches n+GRID_P
        n += GRID_P;
        if (n >= NUM_NODES) break;
        step(n, bufB, gBa, gBb, bufA, gAa, gAb);           // prefetches n+GRID_P
        n += GRID_P;
        if (n >= NUM_NODES) break;
    }
}

// ---------------------------------------------------------------------------
extern "C" void kernel_launch(void* const* d_in, const int* in_sizes, int n_in,
                              void* d_out, int out_size)
{
    const float* x      = (const float*)d_in[0];   // [2048, 64]
    const float* memes  = (const float*)d_in[1];   // [8192, 64]
    const int*   idx    = (const int*)  d_in[2];   // [8192, 32]
    const float* vocab  = (const float*)d_in[3];   // [8192, 64, 256]
    const float* raw_sc = (const float*)d_in[4];   // [1]
    const float* raw_sh = (const float*)d_in[5];   // [1]
    float* out = (float*)d_out;

    gather_kernel<<<NUM_NODES / 2, 256>>>(x, memes, idx);
    stats_kernel<<<1, 256>>>();
    remix_kernel<<<GRID_P, RTHREADS>>>(vocab, raw_sc, raw_sh, out);
}

// round 10
// speedup vs baseline: 1.3195x; 1.0428x over previous
#include <cuda_runtime.h>
#include <math.h>

#define NUM_NODES   8192
#define MEME_DIM    64
#define VISION      2048
#define K_IN        32
#define VOCAB_N     256
#define G_TOT       (NUM_NODES * MEME_DIM)
#define TILE_F4     4096                         // float4s per tile (64*256/4)
#define GRID_P      148                          // persistent CTAs (1/SM)
#define RTHREADS    512

// Scratch (device globals; no allocation allowed)
__device__ float  d_g_raw[G_TOT];
__device__ float2 d_partials[NUM_NODES];
__device__ float  d_stats[2];  // [0]=mean, [1]=inv_std

__device__ __forceinline__ float fast_tanh(float x) {
    float r;
    asm("tanh.approx.f32 %0, %1;" : "=f"(r) : "f"(x));
    return r;
}

// ---------------------------------------------------------------------------
// Kernel 1: gather + mean. 2 nodes per 256-thread block; 4-way MLP per thread.
// ---------------------------------------------------------------------------
__global__ __launch_bounds__(256) void gather_kernel(
    const float* __restrict__ x,          // [2048, 64]
    const float* __restrict__ memes,      // [8192, 64]
    const int*   __restrict__ idx)        // [8192, 32]
{
    const int tid  = threadIdx.x;
    const int half = tid >> 7;
    const int t    = tid & 127;
    const int n    = blockIdx.x * 2 + half;
    const int f4   = t & 15;
    const int kb   = t >> 4;

    const int* ri = idx + (size_t)n * K_IN;

    float4 acc = make_float4(0.f, 0.f, 0.f, 0.f);
#pragma unroll
    for (int j = 0; j < 4; j++) {
        int r = __ldg(ri + kb + 8 * j);
        const float4* src = (r < VISION)
            ? (const float4*)(x + (size_t)r * MEME_DIM)
            : (const float4*)(memes + (size_t)(r - VISION) * MEME_DIM);
        float4 v = __ldg(src + f4);
        acc.x += v.x; acc.y += v.y; acc.z += v.z; acc.w += v.w;
    }

    __shared__ float4 red[256];
    red[tid] = acc;
    __syncthreads();
    if (t < 64) {
        float4 b = red[tid + 64];
        red[tid].x += b.x; red[tid].y += b.y; red[tid].z += b.z; red[tid].w += b.w;
    }
    __syncthreads();
    if (t < 32) {
        float4 b = red[tid + 32];
        red[tid].x += b.x; red[tid].y += b.y; red[tid].z += b.z; red[tid].w += b.w;
    }
    __syncthreads();
    if (t < 16) {
        float4 a = red[tid], b = red[tid + 16];
        float4 g;
        g.x = (a.x + b.x) * (1.f / 32.f);
        g.y = (a.y + b.y) * (1.f / 32.f);
        g.z = (a.z + b.z) * (1.f / 32.f);
        g.w = (a.w + b.w) * (1.f / 32.f);
        ((float4*)(d_g_raw + (size_t)n * MEME_DIM))[t] = g;

        float s = g.x + g.y + g.z + g.w;
        float q = g.x * g.x + g.y * g.y + g.z * g.z + g.w * g.w;
#pragma unroll
        for (int o = 8; o > 0; o >>= 1) {
            s += __shfl_down_sync(0xffffu, s, o, 16);
            q += __shfl_down_sync(0xffffu, q, o, 16);
        }
        if (t == 0) d_partials[n] = make_float2(s, q);
    }
}

// ---------------------------------------------------------------------------
// Kernel 2: reduce partials -> global mean / inv_std (ddof=1), deterministic
// ---------------------------------------------------------------------------
__global__ __launch_bounds__(256) void stats_kernel()
{
    __shared__ double ssum[256], ssq[256];
    const int tid = threadIdx.x;
    double s = 0.0, q = 0.0;
    for (int i = tid; i < NUM_NODES; i += 256) {
        float2 p = d_partials[i];
        s += (double)p.x;
        q += (double)p.y;
    }
    ssum[tid] = s; ssq[tid] = q;
    __syncthreads();
    for (int st = 128; st > 0; st >>= 1) {
        if (tid < st) { ssum[tid] += ssum[tid + st]; ssq[tid] += ssq[tid + st]; }
        __syncthreads();
    }
    if (tid == 0) {
        const double N = (double)G_TOT;
        double mean = ssum[0] / N;
        double var  = (ssq[0] - ssum[0] * ssum[0] / N) / (N - 1.0);
        d_stats[0] = (float)mean;
        d_stats[1] = (float)(1.0 / sqrt(var));
    }
}

// ---------------------------------------------------------------------------
// Kernel 3: fused remix, register-resident vocab. Persistent 148x512.
// Changes vs prior: prefetch issued at TOP of step; stats across warps 0-3
// (2 columns/lane, float2) with named mini-barriers.
// ---------------------------------------------------------------------------
struct RemixSmem {
    float  pd[8 * 256];    // 8KB  dot partials [ch][col]
    float  po[64 * 64];    // 16KB out partials [e][c4]
    float  fs[256];        // 1KB  fractions
    float  ws[4], wq[4], wp[4];
};

__global__ __launch_bounds__(RTHREADS, 1) void remix_kernel(
    const float* __restrict__ vocab,       // [8192, 64, 256]
    const float* __restrict__ raw_sc,      // [1]
    const float* __restrict__ raw_sh,      // [1]
    float*       __restrict__ out)         // [8192, 64]
{
    __shared__ RemixSmem sm;

    const int tid  = threadIdx.x;
    const int lane = tid & 31, w = tid >> 5;
    const int c4   = tid & 63;     // float4 column group
    const int ch   = tid >> 6;     // e-chunk 0..7

    const float sc     = __expf(__ldg(raw_sc));
    const float inv_sc = __fdividef(1.f, sc);
    const float lnsh   = __ldg(raw_sh);
    const float mean   = d_stats[0], istd = d_stats[1];

    const float4* v4 = (const float4*)vocab;

    auto step = [&](int n, float4 (&cur)[8], float4& ga, float4& gb,
                    float4 (&nxt)[8], float4& gna, float4& gnb) {
        // ---- prefetch n+GRID_P FIRST (max latency-hiding window).
        //      WAR on nxt regs is per-thread: last read was previous step. ----
        const int nn = n + GRID_P;
        if (nn < NUM_NODES) {
            const float4* src = v4 + (size_t)nn * TILE_F4 + c4;
#pragma unroll
            for (int j = 0; j < 8; j++)
                nxt[j] = __ldcs(src + (ch * 8 + j) * 64);
            const float4* g4n = (const float4*)(d_g_raw + (size_t)nn * MEME_DIM);
            gna = __ldg(g4n + ch * 2);
            gnb = __ldg(g4n + ch * 2 + 1);
        }

        // standardize this tile's g (loaded during previous step)
        float gr[8];
        gr[0] = (ga.x - mean) * istd; gr[1] = (ga.y - mean) * istd;
        gr[2] = (ga.z - mean) * istd; gr[3] = (ga.w - mean) * istd;
        gr[4] = (gb.x - mean) * istd; gr[5] = (gb.y - mean) * istd;
        gr[6] = (gb.z - mean) * istd; gr[7] = (gb.w - mean) * istd;

        // ---- phase B: dot partials over this thread's 8 e's ----
        {
            float4 a = make_float4(0.f, 0.f, 0.f, 0.f);
#pragma unroll
            for (int j = 0; j < 8; j++) {
                a.x = fmaf(gr[j], cur[j].x, a.x);
                a.y = fmaf(gr[j], cur[j].y, a.y);
                a.z = fmaf(gr[j], cur[j].z, a.z);
                a.w = fmaf(gr[j], cur[j].w, a.w);
            }
            ((float4*)sm.pd)[ch * 64 + c4] = a;
        }
        __syncthreads();                                   // barrier 1

        // ---- stats + fractions on warps 0-3: lane t owns cols 2t, 2t+1 ----
        if (tid < 128) {
            const float2* pd2 = (const float2*)sm.pd;
            float d0 = 0.f, d1 = 0.f;
#pragma unroll
            for (int k = 0; k < 8; k++) {
                float2 p = pd2[k * 128 + tid];
                d0 += p.x; d1 += p.y;
            }
            float s = d0 + d1;
            float q = d0 * d0 + d1 * d1;
#pragma unroll
            for (int o = 16; o > 0; o >>= 1) {
                s += __shfl_down_sync(0xffffffffu, s, o);
                q += __shfl_down_sync(0xffffffffu, q, o);
            }
            if (lane == 0) { sm.ws[w] = s; sm.wq[w] = q; }
            asm volatile("bar.sync 8, 128;" ::: "memory");
            const float bsum = sm.ws[0] + sm.ws[1] + sm.ws[2] + sm.ws[3];
            const float bsq  = sm.wq[0] + sm.wq[1] + sm.wq[2] + sm.wq[3];

            const float m = bsum * (1.f / 256.f);
            float var = (bsq - bsum * bsum * (1.f / 256.f)) * (1.f / 255.f);
            var = fmaxf(var, 0.f);
            const float inv_sd = __fdividef(1.f, sqrtf(var) + 0.001f);

            float p0 = __expf(fast_tanh((d0 - m) * inv_sd * inv_sc) * sc * lnsh);
            float p1 = __expf(fast_tanh((d1 - m) * inv_sd * inv_sc) * sc * lnsh);

            float ps = p0 + p1;
#pragma unroll
            for (int o = 16; o > 0; o >>= 1)
                ps += __shfl_down_sync(0xffffffffu, ps, o);
            if (lane == 0) sm.wp[w] = ps;
            asm volatile("bar.sync 8, 128;" ::: "memory");
            const float psum = sm.wp[0] + sm.wp[1] + sm.wp[2] + sm.wp[3];
            const float inv_psum = __fdividef(1.f, psum + 0.001f);

            ((float2*)sm.fs)[tid] = make_float2(p0 * inv_psum, p1 * inv_psum);
        }
        __syncthreads();                                   // barrier 2

        // ---- phase E: out partials from register-resident vocab ----
        {
            const float4 f = ((const float4*)sm.fs)[c4];
#pragma unroll
            for (int j = 0; j < 8; j++) {
                float p = cur[j].x * f.x + cur[j].y * f.y
                        + cur[j].z * f.z + cur[j].w * f.w;
                sm.po[(ch * 8 + j) * 64 + c4] = p;
            }
        }
        __syncthreads();                                   // barrier 3

        // ---- final reduce: 8 threads per e ----
        {
            const int eo = tid >> 3, p8 = tid & 7;
            const float4* pr = (const float4*)(sm.po + eo * 64 + p8 * 8);
            const float4 r0 = pr[0], r1 = pr[1];
            float s = r0.x + r0.y + r0.z + r0.w + r1.x + r1.y + r1.z + r1.w;
            s += __shfl_down_sync(0xffffffffu, s, 4, 8);
            s += __shfl_down_sync(0xffffffffu, s, 2, 8);
            s += __shfl_down_sync(0xffffffffu, s, 1, 8);
            if (p8 == 0) out[(size_t)n * MEME_DIM + eo] = s;
        }
        // no end barrier: next step's barrier 1 orders smem reuse
    };

    // -------- preload tile n0 --------
    const int n0 = blockIdx.x;
    float4 bufA[8], bufB[8];
    float4 gAa, gAb, gBa, gBb;
    {
        const float4* src = v4 + (size_t)n0 * TILE_F4 + c4;
#pragma unroll
        for (int j = 0; j < 8; j++)
            bufA[j] = __ldcs(src + (ch * 8 + j) * 64);
        const float4* g4 = (const float4*)(d_g_raw + (size_t)n0 * MEME_DIM);
        gAa = __ldg(g4 + ch * 2);
        gAb = __ldg(g4 + ch * 2 + 1);
    }

    int n = n0;
    while (true) {
        step(n, bufA, gAa, gAb, bufB, gBa, gBb);
        n += GRID_P;
        if (n >= NUM_NODES) break;
        step(n, bufB, gBa, gBb, bufA, gAa, gAb);
        n += GRID_P;
        if (n >= NUM_NODES) break;
    }
}

// ---------------------------------------------------------------------------
extern "C" void kernel_launch(void* const* d_in, const int* in_sizes, int n_in,
                              void* d_out, int out_size)
{
    const float* x      = (const float*)d_in[0];   // [2048, 64]
    const float* memes  = (const float*)d_in[1];   // [8192, 64]
    const int*   idx    = (const int*)  d_in[2];   // [8192, 32]
    const float* vocab  = (const float*)d_in[3];   // [8192, 64, 256]
    const float* raw_sc = (const float*)d_in[4];   // [1]
    const float* raw_sh = (const float*)d_in[5];   // [1]
    float* out = (float*)d_out;

    gather_kernel<<<NUM_NODES / 2, 256>>>(x, memes, idx);
    stats_kernel<<<1, 256>>>();
    remix_kernel<<<GRID_P, RTHREADS>>>(vocab, raw_sc, raw_sh, out);
}

// round 11
// speedup vs baseline: 1.3412x; 1.0165x over previous
#include <cuda_runtime.h>
#include <math.h>

#define NUM_NODES   8192
#define MEME_DIM    64
#define VISION      2048
#define K_IN        32
#define VOCAB_N     256
#define G_TOT       (NUM_NODES * MEME_DIM)
#define TILE_F4     4096                         // float4s per tile (64*256/4)
#define GRID_P      148                          // persistent CTAs (1/SM)
#define RTHREADS    512

// Scratch (device globals; no allocation allowed)
__device__ float  d_g_raw[G_TOT];
__device__ float2 d_partials[NUM_NODES];
__device__ float  d_stats[2];  // [0]=mean, [1]=inv_std

__device__ __forceinline__ float fast_tanh(float x) {
    float r;
    asm("tanh.approx.f32 %0, %1;" : "=f"(r) : "f"(x));
    return r;
}

// ---------------------------------------------------------------------------
// Kernel 1: gather + mean. One WARP per node; no block barriers.
// Lane: f4 = lane&15 (float4 slot of 64-float row), kh = lane>>4.
// Lane sums rows k = kh, kh+2, ..., kh+30 (16 gathers, full MLP), then
// pair-sums with lane^16 via shfl_xor.
// ---------------------------------------------------------------------------
__global__ __launch_bounds__(256) void gather_kernel(
    const float* __restrict__ x,          // [2048, 64]
    const float* __restrict__ memes,      // [8192, 64]
    const int*   __restrict__ idx)        // [8192, 32]
{
    const int wid  = threadIdx.x >> 5;
    const int lane = threadIdx.x & 31;
    const int n    = blockIdx.x * 8 + wid;
    const int f4   = lane & 15;
    const int kh   = lane >> 4;

    const int myidx = __ldg(idx + (size_t)n * K_IN + lane);

    const float4* x4 = (const float4*)x;
    const float4* m4 = (const float4*)memes;

    float4 acc = make_float4(0.f, 0.f, 0.f, 0.f);
#pragma unroll
    for (int j = 0; j < 16; j++) {
        const int r = __shfl_sync(0xffffffffu, myidx, kh + 2 * j);
        const float4* src = (r < VISION) ? (x4 + (size_t)r * 16)
                                         : (m4 + (size_t)(r - VISION) * 16);
        const float4 v = __ldg(src + f4);
        acc.x += v.x; acc.y += v.y; acc.z += v.z; acc.w += v.w;
    }

    // pair-sum across the two k-halves (lane <-> lane^16)
    acc.x += __shfl_xor_sync(0xffffffffu, acc.x, 16);
    acc.y += __shfl_xor_sync(0xffffffffu, acc.y, 16);
    acc.z += __shfl_xor_sync(0xffffffffu, acc.z, 16);
    acc.w += __shfl_xor_sync(0xffffffffu, acc.w, 16);

    float4 g;
    g.x = acc.x * (1.f / 32.f); g.y = acc.y * (1.f / 32.f);
    g.z = acc.z * (1.f / 32.f); g.w = acc.w * (1.f / 32.f);

    if (kh == 0)
        ((float4*)(d_g_raw + (size_t)n * MEME_DIM))[f4] = g;

    // per-node sum / sumsq partials (reduce over the 16 kh==0 lanes; the
    // kh==1 half holds identical values after the xor pair-sum, so reduce
    // with width 16 and let lane 0 write)
    float s = g.x + g.y + g.z + g.w;
    float q = g.x * g.x + g.y * g.y + g.z * g.z + g.w * g.w;
#pragma unroll
    for (int o = 8; o > 0; o >>= 1) {
        s += __shfl_down_sync(0xffffffffu, s, o, 16);
        q += __shfl_down_sync(0xffffffffu, q, o, 16);
    }
    if (lane == 0) d_partials[n] = make_float2(s, q);
}

// ---------------------------------------------------------------------------
// Kernel 2: reduce partials -> global mean / inv_std (ddof=1), deterministic
// ---------------------------------------------------------------------------
__global__ __launch_bounds__(256) void stats_kernel()
{
    __shared__ double ssum[256], ssq[256];
    const int tid = threadIdx.x;
    double s = 0.0, q = 0.0;
    for (int i = tid; i < NUM_NODES; i += 256) {
        float2 p = d_partials[i];
        s += (double)p.x;
        q += (double)p.y;
    }
    ssum[tid] = s; ssq[tid] = q;
    __syncthreads();
    for (int st = 128; st > 0; st >>= 1) {
        if (tid < st) { ssum[tid] += ssum[tid + st]; ssq[tid] += ssq[tid + st]; }
        __syncthreads();
    }
    if (tid == 0) {
        const double N = (double)G_TOT;
        double mean = ssum[0] / N;
        double var  = (ssq[0] - ssum[0] * ssum[0] / N) / (N - 1.0);
        d_stats[0] = (float)mean;
        d_stats[1] = (float)(1.0 / sqrt(var));
    }
}

// ---------------------------------------------------------------------------
// Kernel 3: fused remix, register-resident vocab, persistent 148x512.
// 2 barriers per tile: output reduction of tile i-1 runs on threads 128-383
// concurrently with stats of tile i (threads 0-127). Drain after loop.
// ---------------------------------------------------------------------------
struct RemixSmem {
    float  pd[8 * 256];    // 8KB  dot partials [ch][col]
    float  po[64 * 64];    // 16KB out partials [e][c4]
    float  fs[256];        // 1KB  fractions
    float  ws[4], wq[4], wp[4];
};

__global__ __launch_bounds__(RTHREADS, 1) void remix_kernel(
    const float* __restrict__ vocab,       // [8192, 64, 256]
    const float* __restrict__ raw_sc,      // [1]
    const float* __restrict__ raw_sh,      // [1]
    float*       __restrict__ out)         // [8192, 64]
{
    __shared__ RemixSmem sm;

    const int tid  = threadIdx.x;
    const int lane = tid & 31, w = tid >> 5;
    const int c4   = tid & 63;     // float4 column group
    const int ch   = tid >> 6;     // e-chunk 0..7

    const float sc     = __expf(__ldg(raw_sc));
    const float inv_sc = __fdividef(1.f, sc);
    const float lnsh   = __ldg(raw_sh);
    const float mean   = d_stats[0], istd = d_stats[1];

    const float4* v4 = (const float4*)vocab;

    // deferred output reduction of the previous tile (threads 128..383)
    auto reduce_prev = [&](int n_prev) {
        const int t  = tid - 128;           // 0..255
        const int eo = t >> 2;              // 0..63
        const int p4 = t & 3;               // 4 threads per e
        const float4* pr = (const float4*)(sm.po + eo * 64 + p4 * 16);
        const float4 r0 = pr[0], r1 = pr[1], r2 = pr[2], r3 = pr[3];
        float s = r0.x + r0.y + r0.z + r0.w + r1.x + r1.y + r1.z + r1.w
                + r2.x + r2.y + r2.z + r2.w + r3.x + r3.y + r3.z + r3.w;
        s += __shfl_down_sync(0xffffffffu, s, 2, 4);
        s += __shfl_down_sync(0xffffffffu, s, 1, 4);
        if (p4 == 0) out[(size_t)n_prev * MEME_DIM + eo] = s;
    };

    auto step = [&](int n, bool has_prev, float4 (&cur)[8], float4& ga, float4& gb,
                    float4 (&nxt)[8], float4& gna, float4& gnb) {
        // ---- prefetch n+GRID_P first (max latency-hiding window) ----
        const int nn = n + GRID_P;
        if (nn < NUM_NODES) {
            const float4* src = v4 + (size_t)nn * TILE_F4 + c4;
#pragma unroll
            for (int j = 0; j < 8; j++)
                nxt[j] = __ldcs(src + (ch * 8 + j) * 64);
            const float4* g4n = (const float4*)(d_g_raw + (size_t)nn * MEME_DIM);
            gna = __ldg(g4n + ch * 2);
            gnb = __ldg(g4n + ch * 2 + 1);
        }

        // standardize this tile's g
        float gr[8];
        gr[0] = (ga.x - mean) * istd; gr[1] = (ga.y - mean) * istd;
        gr[2] = (ga.z - mean) * istd; gr[3] = (ga.w - mean) * istd;
        gr[4] = (gb.x - mean) * istd; gr[5] = (gb.y - mean) * istd;
        gr[6] = (gb.z - mean) * istd; gr[7] = (gb.w - mean) * istd;

        // ---- phase B: dot partials over this thread's 8 e's ----
        {
            float4 a = make_float4(0.f, 0.f, 0.f, 0.f);
#pragma unroll
            for (int j = 0; j < 8; j++) {
                a.x = fmaf(gr[j], cur[j].x, a.x);
                a.y = fmaf(gr[j], cur[j].y, a.y);
                a.z = fmaf(gr[j], cur[j].z, a.z);
                a.w = fmaf(gr[j], cur[j].w, a.w);
            }
            ((float4*)sm.pd)[ch * 64 + c4] = a;
        }
        __syncthreads();                                   // barrier 1

        if (tid < 128) {
            // ---- stats + fractions: lane t owns cols 2t, 2t+1 ----
            const float2* pd2 = (const float2*)sm.pd;
            float d0 = 0.f, d1 = 0.f;
#pragma unroll
            for (int k = 0; k < 8; k++) {
                float2 p = pd2[k * 128 + tid];
                d0 += p.x; d1 += p.y;
            }
            float s = d0 + d1;
            float q = d0 * d0 + d1 * d1;
#pragma unroll
            for (int o = 16; o > 0; o >>= 1) {
                s += __shfl_down_sync(0xffffffffu, s, o);
                q += __shfl_down_sync(0xffffffffu, q, o);
            }
            if (lane == 0) { sm.ws[w] = s; sm.wq[w] = q; }
            asm volatile("bar.sync 8, 128;" ::: "memory");
            const float bsum = sm.ws[0] + sm.ws[1] + sm.ws[2] + sm.ws[3];
            const float bsq  = sm.wq[0] + sm.wq[1] + sm.wq[2] + sm.wq[3];

            const float m = bsum * (1.f / 256.f);
            float var = (bsq - bsum * bsum * (1.f / 256.f)) * (1.f / 255.f);
            var = fmaxf(var, 0.f);
            const float inv_sd = __fdividef(1.f, sqrtf(var) + 0.001f);

            float p0 = __expf(fast_tanh((d0 - m) * inv_sd * inv_sc) * sc * lnsh);
            float p1 = __expf(fast_tanh((d1 - m) * inv_sd * inv_sc) * sc * lnsh);

            float ps = p0 + p1;
#pragma unroll
            for (int o = 16; o > 0; o >>= 1)
                ps += __shfl_down_sync(0xffffffffu, ps, o);
            if (lane == 0) sm.wp[w] = ps;
            asm volatile("bar.sync 8, 128;" ::: "memory");
            const float psum = sm.wp[0] + sm.wp[1] + sm.wp[2] + sm.wp[3];
            const float inv_psum = __fdividef(1.f, psum + 0.001f);

            ((float2*)sm.fs)[tid] = make_float2(p0 * inv_psum, p1 * inv_psum);
        } else if (tid < 384 && has_prev) {
            // ---- concurrent: reduce + store output of tile n-GRID_P ----
            reduce_prev(n - GRID_P);
        }
        __syncthreads();                                   // barrier 2

        // ---- phase E: out partials from register-resident vocab ----
        {
            const float4 f = ((const float4*)sm.fs)[c4];
#pragma unroll
            for (int j = 0; j < 8; j++) {
                float p = cur[j].x * f.x + cur[j].y * f.y
                        + cur[j].z * f.z + cur[j].w * f.w;
                sm.po[(ch * 8 + j) * 64 + c4] = p;
            }
        }
        // no barrier: next step's barrier 1 orders po reads; drain handles last
    };

    // -------- preload tile n0 --------
    const int n0 = blockIdx.x;
    float4 bufA[8], bufB[8];
    float4 gAa, gAb, gBa, gBb;
    {
        const float4* src = v4 + (size_t)n0 * TILE_F4 + c4;
#pragma unroll
        for (int j = 0; j < 8; j++)
            bufA[j] = __ldcs(src + (ch * 8 + j) * 64);
        const float4* g4 = (const float4*)(d_g_raw + (size_t)n0 * MEME_DIM);
        gAa = __ldg(g4 + ch * 2);
        gAb = __ldg(g4 + ch * 2 + 1);
    }

    int n = n0;
    int n_last = n0;
    bool first = true;
    while (true) {
        step(n, !first, bufA, gAa, gAb, bufB, gBa, gBb);
        n_last = n; first = false;
        n += GRID_P;
        if (n >= NUM_NODES) break;
        step(n, true, bufB, gBa, gBb, bufA, gAa, gAb);
        n_last = n;
        n += GRID_P;
        if (n >= NUM_NODES) break;
    }

    // -------- drain: reduce + store the final tile's output --------
    __syncthreads();
    if (tid >= 128 && tid < 384) reduce_prev(n_last);
}

// ---------------------------------------------------------------------------
extern "C" void kernel_launch(void* const* d_in, const int* in_sizes, int n_in,
                              void* d_out, int out_size)
{
    const float* x      = (const float*)d_in[0];   // [2048, 64]
    const float* memes  = (const float*)d_in[1];   // [8192, 64]
    const int*   idx    = (const int*)  d_in[2];   // [8192, 32]
    const float* vocab  = (const float*)d_in[3];   // [8192, 64, 256]
    const float* raw_sc = (const float*)d_in[4];   // [1]
    const float* raw_sh = (const float*)d_in[5];   // [1]
    float* out = (float*)d_out;

    gather_kernel<<<NUM_NODES / 8, 256>>>(x, memes, idx);
    stats_kernel<<<1, 256>>>();
    remix_kernel<<<GRID_P, RTHREADS>>>(vocab, raw_sc, raw_sh, out);
}